// round 1
// baseline (speedup 1.0000x reference)
#include <cuda_runtime.h>
#include <cstdint>

// Problem constants (fixed shapes from reference)
#define B_  8
#define C_  21
#define D_  64
#define O_  128
#define HW_ 65536
#define N_TOT (B_ * HW_)   // 524288

typedef unsigned long long ull;

// ---------------- device scratch (static allocation; no cudaMalloc) ----------
__device__ float g_S[B_ * C_];            // per-batch mask sums
__device__ float g_G[B_ * C_ * C_];       // per-batch mask Gram matrices
__device__ float g_W2[B_ * O_ * C_];      // combined weights  [b][o][c]
__device__ ull   g_A2[B_ * C_ * O_];      // alpha-scaled weights, f32x2-duplicated, [b][c][o]
__device__ ull   g_bias2[O_];             // fused bias, f32x2-duplicated

// ---------------- kernel Z: zero the atomic accumulators ---------------------
__global__ void kzero() {
    for (int i = threadIdx.x; i < B_ * C_ * C_; i += blockDim.x) g_G[i] = 0.f;
    for (int i = threadIdx.x; i < B_ * C_;      i += blockDim.x) g_S[i] = 0.f;
}

// ---------------- kernel A: mask sums + Gram --------------------------------
// grid (32, B), 672 threads = 21 warps. Warp w owns Gram column c=w.
// Block processes 2048 contiguous pixels, staged in tiles of 256 through smem.
#define TP_ 256
__global__ __launch_bounds__(672) void kstats(const float* __restrict__ mask) {
    __shared__ float sh[C_ * (TP_ + 1)];
    const int b = blockIdx.y;
    const int base0 = blockIdx.x * 2048;
    const int w = threadIdx.x >> 5;
    const int lane = threadIdx.x & 31;

    float acc[C_];
#pragma unroll
    for (int r = 0; r < C_; r++) acc[r] = 0.f;
    float ssum = 0.f;

    const float* mb = mask + (size_t)b * C_ * HW_;

    for (int t = 0; t < 2048; t += TP_) {
        const int base = base0 + t;
        __syncthreads();
        // stage 21 x 256 tile (coalesced: p contiguous per c-row)
        for (int idx = threadIdx.x; idx < C_ * TP_; idx += 672) {
            int c = idx / TP_, p = idx - c * TP_;
            sh[c * (TP_ + 1) + p] = mb[(size_t)c * HW_ + base + p];
        }
        __syncthreads();
        // warp w accumulates G[:, w] and S[w]
        for (int p = lane; p < TP_; p += 32) {
            float mc = sh[w * (TP_ + 1) + p];
            ssum += mc;
#pragma unroll
            for (int r = 0; r < C_; r++) acc[r] += sh[r * (TP_ + 1) + p] * mc;
        }
    }

    // warp reductions + global atomics
#pragma unroll
    for (int r = 0; r < C_; r++) {
        float v = acc[r];
        for (int off = 16; off; off >>= 1) v += __shfl_xor_sync(0xffffffffu, v, off);
        if (lane == 0) atomicAdd(&g_G[(b * C_ + w) * C_ + r], v);
    }
    {
        float v = ssum;
        for (int off = 16; off; off >>= 1) v += __shfl_xor_sync(0xffffffffu, v, off);
        if (lane == 0) atomicAdd(&g_S[b * C_ + w], v);
    }
}

// ---------------- kernel B: W2, analytic BN stats, fused coefficients -------
// single block, 256 threads
__global__ __launch_bounds__(256) void kprep(const float* __restrict__ feat,
                                             const float* __restrict__ conv_w,
                                             const float* __restrict__ conv_b,
                                             const float* __restrict__ gamma,
                                             const float* __restrict__ beta) {
    __shared__ float salpha[O_];
    const int tid = threadIdx.x;

    // Phase 1: W2[b][o][c] = <conv_w[o,:], feat[b,c,:]>
    for (int idx = tid; idx < B_ * O_ * C_; idx += 256) {
        int b = idx / (O_ * C_);
        int rem = idx - b * (O_ * C_);
        int o = rem / C_;
        int c = rem - o * C_;
        const float* wr = conv_w + o * D_;
        const float* fr = feat + (b * C_ + c) * D_;
        float s = 0.f;
#pragma unroll 8
        for (int d = 0; d < D_; d++) s += wr[d] * fr[d];
        g_W2[idx] = s;
    }
    __syncthreads();  // also makes global writes visible within block

    // Phase 2: per-channel analytic BN stats
    if (tid < O_) {
        const int o = tid;
        float sumY = 0.f, sumQ = 0.f;
        for (int b = 0; b < B_; b++) {
            float w[C_];
#pragma unroll
            for (int c = 0; c < C_; c++) w[c] = g_W2[(b * O_ + o) * C_ + c];
#pragma unroll
            for (int c = 0; c < C_; c++) sumY += w[c] * g_S[b * C_ + c];
            for (int c = 0; c < C_; c++) {
                float t = 0.f;
#pragma unroll
                for (int c2 = 0; c2 < C_; c2++) t += w[c2] * g_G[(b * C_ + c) * C_ + c2];
                sumQ += w[c] * t;
            }
        }
        const float invN = 1.f / (float)N_TOT;
        const float b0 = conv_b[o];
        const float es = sumY * invN;                 // E[s]
        const float mean = b0 + es;                   // E[y]
        const float ey2 = sumQ * invN + 2.f * b0 * es + b0 * b0;
        const float var = ey2 - mean * mean;
        const float alpha = gamma[o] * rsqrtf(var + 1e-5f);
        salpha[o] = alpha;
        const float bias2 = beta[o] + alpha * (b0 - mean);
        unsigned int ub = __float_as_uint(bias2);
        g_bias2[o] = ((ull)ub << 32) | ub;
    }
    __syncthreads();

    // Phase 3: duplicated f32x2 coefficients, layout [b][c][o]
    for (int idx = tid; idx < B_ * C_ * O_; idx += 256) {
        int b = idx / (C_ * O_);
        int rem = idx - b * (C_ * O_);
        int c = rem / O_;
        int o = rem - c * O_;
        float v = salpha[o] * g_W2[(b * O_ + o) * C_ + c];
        unsigned int uv = __float_as_uint(v);
        g_A2[idx] = ((ull)uv << 32) | uv;
    }
}

// ---------------- kernel C: fused K=21 GEMM + BN + ReLU (f32x2 packed) ------
// grid (HW/512, B), 256 threads; each thread owns one pixel-pair x 128 channels
__global__ __launch_bounds__(256) void kmain(const float* __restrict__ mask,
                                             float* __restrict__ out) {
    __shared__ ull sA2[C_ * O_];   // 21*128*8 = 21504 B, broadcast reads
    __shared__ ull sBias[O_];

    const int b = blockIdx.y;
    const int tid = threadIdx.x;

    for (int idx = tid; idx < C_ * O_; idx += 256) sA2[idx] = g_A2[b * C_ * O_ + idx];
    if (tid < O_) sBias[tid] = g_bias2[tid];
    __syncthreads();

    const int pix = blockIdx.x * 512 + tid * 2;

    // load 21 mask pixel-pairs into registers (coalesced LDG.64)
    const float* mpb = mask + (size_t)b * C_ * HW_ + pix;
    ull m[C_];
#pragma unroll
    for (int c = 0; c < C_; c++)
        m[c] = *reinterpret_cast<const ull*>(mpb + (size_t)c * HW_);

    float* outp = out + (size_t)b * O_ * HW_ + pix;

#pragma unroll
    for (int oc = 0; oc < 4; oc++) {
        ull acc[32];
#pragma unroll
        for (int j = 0; j < 32; j++) acc[j] = sBias[oc * 32 + j];

#pragma unroll
        for (int c = 0; c < C_; c++) {
#pragma unroll
            for (int j = 0; j < 32; j++) {
                asm("fma.rn.f32x2 %0, %1, %2, %0;"
                    : "+l"(acc[j])
                    : "l"(sA2[c * O_ + oc * 32 + j]), "l"(m[c]));
            }
        }

#pragma unroll
        for (int j = 0; j < 32; j++) {
            float lo = __uint_as_float((unsigned)(acc[j] & 0xffffffffu));
            float hi = __uint_as_float((unsigned)(acc[j] >> 32));
            float2 v = make_float2(fmaxf(lo, 0.f), fmaxf(hi, 0.f));
            *reinterpret_cast<float2*>(outp + (size_t)(oc * 32 + j) * HW_) = v;
        }
    }
}

// ---------------- launcher ---------------------------------------------------
extern "C" void kernel_launch(void* const* d_in, const int* in_sizes, int n_in,
                              void* d_out, int out_size) {
    const float* feat   = (const float*)d_in[0];  // [8,21,64]
    const float* mask   = (const float*)d_in[1];  // [8,21,256,256]
    const float* conv_w = (const float*)d_in[2];  // [128,64]
    const float* conv_b = (const float*)d_in[3];  // [128]
    const float* gamma  = (const float*)d_in[4];  // [128]
    const float* beta   = (const float*)d_in[5];  // [128]
    float* out = (float*)d_out;                    // [8,128,256,256]

    kzero<<<1, 256>>>();
    kstats<<<dim3(32, B_), 672>>>(mask);
    kprep<<<1, 256>>>(feat, conv_w, conv_b, gamma, beta);
    kmain<<<dim3(HW_ / 512, B_), 256>>>(mask, out);
}

// round 2
// speedup vs baseline: 2.3796x; 2.3796x over previous
#include <cuda_runtime.h>
#include <cstdint>

#define B_  8
#define C_  21
#define D_  64
#define O_  128
#define HW_ 65536
#define N_TOT (B_ * HW_)

typedef unsigned long long ull;

// ---------------- device scratch ---------------------------------------------
__device__ float g_S[B_ * C_];            // per-batch mask sums
__device__ float g_G[B_ * C_ * C_];       // per-batch mask Gram
__device__ float g_W2[B_ * O_ * C_];      // combined weights [b][o][c]
__device__ ull   g_A2[B_ * C_ * O_];      // alpha*W2, f32x2-dup, [b][c][o]
__device__ ull   g_bias2[O_];             // fused bias, f32x2-dup

// ---------------- kernel Z: zero accumulators --------------------------------
__global__ void kzero() {
    for (int i = threadIdx.x; i < B_ * C_ * C_; i += blockDim.x) g_G[i] = 0.f;
    for (int i = threadIdx.x; i < B_ * C_;      i += blockDim.x) g_S[i] = 0.f;
}

// ---------------- kstats<R0>: register-resident Gram rows [R0, R0+7) ---------
// grid (32, B), 256 threads. Thread owns 7x21 Gram tile + 7 row-sums in regs.
template <int R0>
__global__ __launch_bounds__(256, 1) void kstats(const float* __restrict__ mask) {
    const int b = blockIdx.y;
    const int tid = threadIdx.x;
    const int lane = tid & 31;

    float acc[7][C_];
    float ss[7];
#pragma unroll
    for (int i = 0; i < 7; i++) {
        ss[i] = 0.f;
#pragma unroll
        for (int c = 0; c < C_; c++) acc[i][c] = 0.f;
    }

    const float* mb = mask + (size_t)b * C_ * HW_;
    const int base = blockIdx.x * 2048;

    for (int it = 0; it < 8; it++) {
        const int p = base + it * 256 + tid;
        float m[C_];
#pragma unroll
        for (int c = 0; c < C_; c++) m[c] = __ldg(mb + (size_t)c * HW_ + p);
#pragma unroll
        for (int i = 0; i < 7; i++) {
            const float mr = m[R0 + i];
            ss[i] += mr;
#pragma unroll
            for (int c = 0; c < C_; c++) acc[i][c] = fmaf(mr, m[c], acc[i][c]);
        }
    }

    // warp shfl reduce + global atomics (lane 0)
#pragma unroll
    for (int i = 0; i < 7; i++) {
#pragma unroll
        for (int c = 0; c < C_; c++) {
            float v = acc[i][c];
#pragma unroll
            for (int off = 16; off; off >>= 1) v += __shfl_xor_sync(0xffffffffu, v, off);
            if (lane == 0) atomicAdd(&g_G[(b * C_ + (R0 + i)) * C_ + c], v);
        }
        float v = ss[i];
#pragma unroll
        for (int off = 16; off; off >>= 1) v += __shfl_xor_sync(0xffffffffu, v, off);
        if (lane == 0) atomicAdd(&g_S[b * C_ + (R0 + i)], v);
    }
}

// ---------------- kprep1: W2[b][o][c] via smem-staged dots -------------------
// grid (B), 256 threads
__global__ __launch_bounds__(256) void kprep1(const float* __restrict__ feat,
                                              const float* __restrict__ conv_w) {
    __shared__ float sF[C_ * 65];   // padded rows, conflict-free
    __shared__ float sW[O_ * D_];
    const int b = blockIdx.x;
    const int tid = threadIdx.x;

    for (int i = tid; i < C_ * D_; i += 256) {
        int c = i >> 6, d = i & 63;
        sF[c * 65 + d] = feat[(b * C_ + c) * D_ + d];
    }
    for (int i = tid; i < O_ * D_; i += 256) sW[i] = conv_w[i];
    __syncthreads();

    for (int idx = tid; idx < O_ * C_; idx += 256) {
        int o = idx / C_, c = idx - o * C_;
        float s = 0.f;
#pragma unroll
        for (int d = 0; d < D_; d++) s = fmaf(sW[o * D_ + d], sF[c * 65 + d], s);
        g_W2[(b * O_ + o) * C_ + c] = s;
    }
}

// ---------------- kprep2: analytic BN stats + fused coefficients -------------
// single block, 256 threads
__global__ __launch_bounds__(256) void kprep2(const float* __restrict__ conv_b,
                                              const float* __restrict__ gamma,
                                              const float* __restrict__ beta) {
    __shared__ float salpha[O_];
    __shared__ float sG[B_ * C_ * C_];
    __shared__ float sS[B_ * C_];
    const int tid = threadIdx.x;

    for (int i = tid; i < B_ * C_ * C_; i += 256) sG[i] = g_G[i];
    for (int i = tid; i < B_ * C_;      i += 256) sS[i] = g_S[i];
    __syncthreads();

    if (tid < O_) {
        const int o = tid;
        float sumY = 0.f, sumQ = 0.f;
        for (int b = 0; b < B_; b++) {
            float w[C_];
#pragma unroll
            for (int c = 0; c < C_; c++) w[c] = g_W2[(b * O_ + o) * C_ + c];
#pragma unroll
            for (int c = 0; c < C_; c++) sumY = fmaf(w[c], sS[b * C_ + c], sumY);
#pragma unroll
            for (int c = 0; c < C_; c++) {
                float t = 0.f;
#pragma unroll
                for (int c2 = 0; c2 < C_; c2++) t = fmaf(w[c2], sG[(b * C_ + c) * C_ + c2], t);
                sumQ = fmaf(w[c], t, sumQ);
            }
        }
        const float invN = 1.f / (float)N_TOT;
        const float b0 = conv_b[o];
        const float es = sumY * invN;
        const float mean = b0 + es;
        const float ey2 = sumQ * invN + 2.f * b0 * es + b0 * b0;
        const float var = ey2 - mean * mean;
        const float alpha = gamma[o] * rsqrtf(var + 1e-5f);
        salpha[o] = alpha;
        const float bias2 = beta[o] + alpha * (b0 - mean);
        const unsigned int ub = __float_as_uint(bias2);
        g_bias2[o] = ((ull)ub << 32) | ub;
    }
    __syncthreads();

    for (int idx = tid; idx < B_ * C_ * O_; idx += 256) {
        int b = idx / (C_ * O_);
        int rem = idx - b * (C_ * O_);
        int c = rem / O_;
        int o = rem - c * O_;
        float v = salpha[o] * g_W2[(b * O_ + o) * C_ + c];
        unsigned int uv = __float_as_uint(v);
        g_A2[idx] = ((ull)uv << 32) | uv;
    }
}

// ---------------- kmain: block-tiled K=21 GEMM + BN + ReLU -------------------
// 512 threads = 16 warps. Block tile: 256 pixels x 128 channels.
// Warp = 8-channel group; thread = 4 pixel-pairs (lane + {0,32,64,96}) x 8 ch.
__global__ __launch_bounds__(512, 1) void kmain(const float* __restrict__ mask,
                                                float* __restrict__ out) {
    __shared__ ull   sA2[C_ * O_];    // 21504 B, [c][o] duplicated pairs
    __shared__ ull   sBias[O_];       // 1024 B
    __shared__ float sM[C_ * 256];    // 21504 B, [c][pixel]

    const int b = blockIdx.y;
    const int p0 = blockIdx.x * 256;
    const int tid = threadIdx.x;
    const int wid = tid >> 5;
    const int lane = tid & 31;

    // stage coefficients
    for (int idx = tid; idx < C_ * O_; idx += 512) sA2[idx] = g_A2[b * C_ * O_ + idx];
    if (tid < O_) sBias[tid] = g_bias2[tid];
    // stage mask tile (float4, coalesced)
    {
        const float* mb = mask + (size_t)b * C_ * HW_ + p0;
        float4* sM4 = reinterpret_cast<float4*>(sM);
        for (int idx = tid; idx < C_ * 64; idx += 512) {
            int c = idx >> 6, q = idx & 63;
            sM4[idx] = reinterpret_cast<const float4*>(mb + (size_t)c * HW_)[q];
        }
    }
    __syncthreads();

    ull acc[4][8];
#pragma unroll
    for (int j = 0; j < 8; j++) {
        ull bv = sBias[wid * 8 + j];
#pragma unroll
        for (int pp = 0; pp < 4; pp++) acc[pp][j] = bv;
    }

    const ull* sMp = reinterpret_cast<const ull*>(sM);   // [c][128 pairs]

#pragma unroll
    for (int c = 0; c < C_; c++) {
        ull mp[4];
#pragma unroll
        for (int pp = 0; pp < 4; pp++) mp[pp] = sMp[c * 128 + lane + pp * 32];
        ull cf[8];
#pragma unroll
        for (int j = 0; j < 8; j++) cf[j] = sA2[c * O_ + wid * 8 + j];
#pragma unroll
        for (int pp = 0; pp < 4; pp++)
#pragma unroll
            for (int j = 0; j < 8; j++)
                asm("fma.rn.f32x2 %0, %1, %2, %0;"
                    : "+l"(acc[pp][j]) : "l"(cf[j]), "l"(mp[pp]));
    }

    // epilogue: ReLU + coalesced 8B stores (lanes -> consecutive pixel pairs)
    float* ob = out + (size_t)b * O_ * HW_ + p0;
#pragma unroll
    for (int j = 0; j < 8; j++) {
        const int o = wid * 8 + j;
#pragma unroll
        for (int pp = 0; pp < 4; pp++) {
            ull a = acc[pp][j];
            float lo = __uint_as_float((unsigned)(a & 0xffffffffu));
            float hi = __uint_as_float((unsigned)(a >> 32));
            float2 v = make_float2(fmaxf(lo, 0.f), fmaxf(hi, 0.f));
            *reinterpret_cast<float2*>(ob + (size_t)o * HW_ + (lane + pp * 32) * 2) = v;
        }
    }
}

// ---------------- launcher ----------------------------------------------------
extern "C" void kernel_launch(void* const* d_in, const int* in_sizes, int n_in,
                              void* d_out, int out_size) {
    const float* feat   = (const float*)d_in[0];
    const float* mask   = (const float*)d_in[1];
    const float* conv_w = (const float*)d_in[2];
    const float* conv_b = (const float*)d_in[3];
    const float* gamma  = (const float*)d_in[4];
    const float* beta   = (const float*)d_in[5];
    float* out = (float*)d_out;

    kzero<<<1, 256>>>();
    kstats<0><<<dim3(32, B_), 256>>>(mask);
    kstats<7><<<dim3(32, B_), 256>>>(mask);
    kstats<14><<<dim3(32, B_), 256>>>(mask);
    kprep1<<<B_, 256>>>(feat, conv_w);
    kprep2<<<1, 256>>>(conv_b, gamma, beta);
    kmain<<<dim3(HW_ / 256, B_), 512>>>(mask, out);
}

// round 3
// speedup vs baseline: 3.8755x; 1.6286x over previous
#include <cuda_runtime.h>
#include <cstdint>

#define B_  8
#define C_  21
#define D_  64
#define O_  128
#define HW_ 65536
#define N_TOT (B_ * HW_)

typedef unsigned long long ull;

// ---------------- device scratch ---------------------------------------------
__device__ float g_S[B_ * C_];            // per-batch mask sums
__device__ float g_G[B_ * C_ * C_];       // per-batch mask Gram (rows computed fully)
__device__ float g_W2[B_ * O_ * C_];      // combined weights [b][o][c]
__device__ ull   g_A2[B_ * C_ * O_];      // alpha*W2, f32x2-dup, [b][c][o]
__device__ ull   g_bias2[O_];             // fused bias, f32x2-dup

// ---------------- kernel Z: zero accumulators --------------------------------
__global__ void kzero() {
    for (int i = threadIdx.x; i < B_ * C_ * C_; i += blockDim.x) g_G[i] = 0.f;
    for (int i = threadIdx.x; i < B_ * C_;      i += blockDim.x) g_S[i] = 0.f;
}

// ---------------- kstats: single launch, 3 row-groups, L2-shared mask --------
// grid (3, 16, B): x = row-group (fastest -> same pixels adjacent in schedule),
// y = pixel chunk (4096 px), z = batch. 256 threads.
// Values per block: 7 rows x 21 cols Gram + 7 sums = 154, reduced via
// 2-level shfl -> smem transpose -> 154-thread final sum -> 1 atomic each.
#define NV_ 154   // 147 gram + 7 sums

template <int R0>
__device__ __forceinline__ void stats_body(const float* __restrict__ mask,
                                           float* __restrict__ sP) {
    const int b = blockIdx.z;
    const int tid = threadIdx.x;
    const int w = tid >> 5;
    const int lane = tid & 31;

    float acc[7][C_];
    float ss[7];
#pragma unroll
    for (int i = 0; i < 7; i++) {
        ss[i] = 0.f;
#pragma unroll
        for (int c = 0; c < C_; c++) acc[i][c] = 0.f;
    }

    const float* mb = mask + (size_t)b * C_ * HW_;
    const int basePair = blockIdx.y * 2048;   // 4096 pixels = 2048 pairs

#pragma unroll 1
    for (int it = 0; it < 8; it++) {
        const int pr = basePair + it * 256 + tid;
        float2 m2[C_];
#pragma unroll
        for (int c = 0; c < C_; c++)
            m2[c] = *reinterpret_cast<const float2*>(mb + (size_t)c * HW_ + pr * 2);
#pragma unroll
        for (int i = 0; i < 7; i++) {
            const float2 mr = m2[R0 + i];
            ss[i] += mr.x + mr.y;
#pragma unroll
            for (int c = 0; c < C_; c++) {
                acc[i][c] = fmaf(mr.x, m2[c].x, acc[i][c]);
                acc[i][c] = fmaf(mr.y, m2[c].y, acc[i][c]);
            }
        }
    }

    // fold 32 -> 8 lanes, stage to smem [value][72... use 65 stride]
#pragma unroll
    for (int i = 0; i < 7; i++) {
#pragma unroll
        for (int c = 0; c < C_; c++) {
            float v = acc[i][c];
            v += __shfl_xor_sync(0xffffffffu, v, 16);
            v += __shfl_xor_sync(0xffffffffu, v, 8);
            if (lane < 8) sP[(i * C_ + c) * 65 + w * 8 + lane] = v;
        }
        float v = ss[i];
        v += __shfl_xor_sync(0xffffffffu, v, 16);
        v += __shfl_xor_sync(0xffffffffu, v, 8);
        if (lane < 8) sP[(147 + i) * 65 + w * 8 + lane] = v;
    }
    __syncthreads();

    // final: thread v sums 64 partials, one atomic
    if (tid < NV_) {
        const float* row = sP + tid * 65;
        float s = 0.f;
#pragma unroll
        for (int k = 0; k < 64; k++) s += row[k];
        if (tid < 147) {
            int i = tid / C_, c = tid - i * C_;
            atomicAdd(&g_G[(b * C_ + (R0 + i)) * C_ + c], s);
        } else {
            atomicAdd(&g_S[b * C_ + (R0 + (tid - 147))], s);
        }
    }
}

__global__ __launch_bounds__(256, 1) void kstats(const float* __restrict__ mask) {
    __shared__ float sP[NV_ * 65];   // ~40 KB
    if (blockIdx.x == 0)      stats_body<0>(mask, sP);
    else if (blockIdx.x == 1) stats_body<7>(mask, sP);
    else                      stats_body<14>(mask, sP);
}

// ---------------- kprep1: W2[b][o][c] via smem-staged dots -------------------
__global__ __launch_bounds__(256) void kprep1(const float* __restrict__ feat,
                                              const float* __restrict__ conv_w) {
    __shared__ float sF[C_ * 65];
    __shared__ float sW[O_ * D_];
    const int b = blockIdx.x;
    const int tid = threadIdx.x;

    for (int i = tid; i < C_ * D_; i += 256) {
        int c = i >> 6, d = i & 63;
        sF[c * 65 + d] = feat[(b * C_ + c) * D_ + d];
    }
    for (int i = tid; i < O_ * D_; i += 256) sW[i] = conv_w[i];
    __syncthreads();

    for (int idx = tid; idx < O_ * C_; idx += 256) {
        int o = idx / C_, c = idx - o * C_;
        float s = 0.f;
#pragma unroll
        for (int d = 0; d < D_; d++) s = fmaf(sW[o * D_ + d], sF[c * 65 + d], s);
        g_W2[(b * O_ + o) * C_ + c] = s;
    }
}

// ---------------- kprep2: analytic BN stats + fused coefficients -------------
__global__ __launch_bounds__(256) void kprep2(const float* __restrict__ conv_b,
                                              const float* __restrict__ gamma,
                                              const float* __restrict__ beta) {
    __shared__ float salpha[O_];
    __shared__ float sG[B_ * C_ * C_];
    __shared__ float sS[B_ * C_];
    const int tid = threadIdx.x;

    for (int i = tid; i < B_ * C_ * C_; i += 256) sG[i] = g_G[i];
    for (int i = tid; i < B_ * C_;      i += 256) sS[i] = g_S[i];
    __syncthreads();

    if (tid < O_) {
        const int o = tid;
        float sumY = 0.f, sumQ = 0.f;
        for (int b = 0; b < B_; b++) {
            float w[C_];
#pragma unroll
            for (int c = 0; c < C_; c++) w[c] = g_W2[(b * O_ + o) * C_ + c];
#pragma unroll
            for (int c = 0; c < C_; c++) sumY = fmaf(w[c], sS[b * C_ + c], sumY);
#pragma unroll
            for (int c = 0; c < C_; c++) {
                float t = 0.f;
#pragma unroll
                for (int c2 = 0; c2 < C_; c2++) t = fmaf(w[c2], sG[(b * C_ + c) * C_ + c2], t);
                sumQ = fmaf(w[c], t, sumQ);
            }
        }
        const float invN = 1.f / (float)N_TOT;
        const float b0 = conv_b[o];
        const float es = sumY * invN;
        const float mean = b0 + es;
        const float ey2 = sumQ * invN + 2.f * b0 * es + b0 * b0;
        const float var = ey2 - mean * mean;
        const float alpha = gamma[o] * rsqrtf(var + 1e-5f);
        salpha[o] = alpha;
        const float bias2 = beta[o] + alpha * (b0 - mean);
        const unsigned int ub = __float_as_uint(bias2);
        g_bias2[o] = ((ull)ub << 32) | ub;
    }
    __syncthreads();

    for (int idx = tid; idx < B_ * C_ * O_; idx += 256) {
        int b = idx / (C_ * O_);
        int rem = idx - b * (C_ * O_);
        int c = rem / O_;
        int o = rem - c * O_;
        float v = salpha[o] * g_W2[(b * O_ + o) * C_ + c];
        unsigned int uv = __float_as_uint(v);
        g_A2[idx] = ((ull)uv << 32) | uv;
    }
}

// ---------------- kmain: block-tiled K=21 GEMM + BN + ReLU -------------------
// 512 threads = 16 warps. Block tile: 256 pixels x 128 channels.
// Warp = 8-channel group. Thread owns 2 quads (4 consecutive px each) at
// quad indices {lane, lane+32} -> conflict-free LDS.128 + STG.128.
__global__ __launch_bounds__(512, 1) void kmain(const float* __restrict__ mask,
                                                float* __restrict__ out) {
    __shared__ ull   sA2[C_ * O_];                      // 21504 B
    __shared__ ull   sBias[O_];                         // 1024 B
    __shared__ __align__(16) float sM[C_ * 256];        // 21504 B

    const int b = blockIdx.y;
    const int p0 = blockIdx.x * 256;
    const int tid = threadIdx.x;
    const int wid = tid >> 5;
    const int lane = tid & 31;

    for (int idx = tid; idx < C_ * O_; idx += 512) sA2[idx] = g_A2[b * C_ * O_ + idx];
    if (tid < O_) sBias[tid] = g_bias2[tid];
    {
        const float* mb = mask + (size_t)b * C_ * HW_ + p0;
        float4* sM4 = reinterpret_cast<float4*>(sM);
        for (int idx = tid; idx < C_ * 64; idx += 512) {
            int c = idx >> 6, q = idx & 63;
            sM4[idx] = reinterpret_cast<const float4*>(mb + (size_t)c * HW_)[q];
        }
    }
    __syncthreads();

    ull acc[2][2][8];   // [quad pp][half][channel j]
#pragma unroll
    for (int j = 0; j < 8; j++) {
        ull bv = sBias[wid * 8 + j];
#pragma unroll
        for (int pp = 0; pp < 2; pp++) { acc[pp][0][j] = bv; acc[pp][1][j] = bv; }
    }

#pragma unroll
    for (int c = 0; c < C_; c++) {
        ull mq[2][2];
#pragma unroll
        for (int pp = 0; pp < 2; pp++) {
            // quad = 16 B at sM + c*1024 + (lane+pp*32)*16  (stride 16B: conflict-free)
            ulonglong2 v = reinterpret_cast<const ulonglong2*>(sM + c * 256)[lane + pp * 32];
            mq[pp][0] = v.x; mq[pp][1] = v.y;
        }
        ull cf[8];
#pragma unroll
        for (int j = 0; j < 8; j++) cf[j] = sA2[c * O_ + wid * 8 + j];   // broadcast
#pragma unroll
        for (int pp = 0; pp < 2; pp++)
#pragma unroll
            for (int h = 0; h < 2; h++)
#pragma unroll
                for (int j = 0; j < 8; j++)
                    asm("fma.rn.f32x2 %0, %1, %2, %0;"
                        : "+l"(acc[pp][h][j]) : "l"(cf[j]), "l"(mq[pp][h]));
    }

    // epilogue: ReLU + STG.128 (warp stores 512 B contiguous per (j, pp))
    float* ob = out + (size_t)b * O_ * HW_ + p0;
#pragma unroll
    for (int j = 0; j < 8; j++) {
        const int o = wid * 8 + j;
        float4* orow = reinterpret_cast<float4*>(ob + (size_t)o * HW_);
#pragma unroll
        for (int pp = 0; pp < 2; pp++) {
            float2 a = *reinterpret_cast<float2*>(&acc[pp][0][j]);
            float2 c2 = *reinterpret_cast<float2*>(&acc[pp][1][j]);
            float4 v = make_float4(fmaxf(a.x, 0.f), fmaxf(a.y, 0.f),
                                   fmaxf(c2.x, 0.f), fmaxf(c2.y, 0.f));
            orow[lane + pp * 32] = v;
        }
    }
}

// ---------------- launcher ----------------------------------------------------
extern "C" void kernel_launch(void* const* d_in, const int* in_sizes, int n_in,
                              void* d_out, int out_size) {
    const float* feat   = (const float*)d_in[0];
    const float* mask   = (const float*)d_in[1];
    const float* conv_w = (const float*)d_in[2];
    const float* conv_b = (const float*)d_in[3];
    const float* gamma  = (const float*)d_in[4];
    const float* beta   = (const float*)d_in[5];
    float* out = (float*)d_out;

    kzero<<<1, 256>>>();
    kstats<<<dim3(3, 16, B_), 256>>>(mask);
    kprep1<<<B_, 256>>>(feat, conv_w);
    kprep2<<<1, 256>>>(conv_b, gamma, beta);
    kmain<<<dim3(HW_ / 256, B_), 512>>>(mask, out);
}

// round 4
// speedup vs baseline: 3.8767x; 1.0003x over previous
#include <cuda_runtime.h>
#include <cstdint>

#define B_  8
#define C_  21
#define D_  64
#define O_  128
#define HW_ 65536
#define N_TOT (B_ * HW_)

typedef unsigned long long ull;
typedef unsigned int uint;

// ---------------- device scratch ---------------------------------------------
#define KS_CHUNKS 32
#define NVAL 462                      // 441 gram + 21 sums
__device__ float g_Gp[KS_CHUNKS * B_ * NVAL];   // per-block stat partials
__device__ float g_W2T[B_ * C_ * O_];           // combined weights [b][c][o]
__device__ ull   g_A2[B_ * C_ * O_];            // alpha*W2, f32x2-dup, [b][c][o]
__device__ ull   g_bias2[O_];                   // fused bias, f32x2-dup

// ---------------- cp.async helpers -------------------------------------------
__device__ __forceinline__ void cp16(void* dst, const void* src) {
    uint s = (uint)__cvta_generic_to_shared(dst);
    asm volatile("cp.async.cg.shared.global [%0], [%1], 16;" :: "r"(s), "l"(src));
}
#define CP_COMMIT() asm volatile("cp.async.commit_group;" ::: "memory")
#define CP_WAIT1()  asm volatile("cp.async.wait_group 1;" ::: "memory")
#define CP_WAIT0()  asm volatile("cp.async.wait_group 0;" ::: "memory")

// ---------------- kstats: mask sums + Gram, one pass over mask ----------------
// grid (32, 8): x = pixel chunk (2048 px), y = batch. 192 threads = 6 warps.
// Warp w owns Gram rows: w<3 ? rows [4w,4w+4) : rows [12+3(w-3), +3).
// Mask tile (21 x 256 px) staged via cp.async double buffer; every warp reads
// the same smem tile -> mask read from DRAM exactly once.
#define KS_TILE 256
#define KS_NT   8      // tiles per block (2048 px)

__global__ __launch_bounds__(192, 2) void kstats(const float* __restrict__ mask) {
    __shared__ __align__(16) float sT[2][C_][KS_TILE];   // 43008 B

    const int b = blockIdx.y;
    const int chunk = blockIdx.x;
    const int tid = threadIdx.x;
    const int wid = tid >> 5;
    const int lane = tid & 31;
    const int nr = (wid < 3) ? 4 : 3;
    const int r0 = (wid < 3) ? wid * 4 : 12 + (wid - 3) * 3;

    const float* mb = mask + (size_t)b * C_ * HW_ + chunk * (KS_TILE * KS_NT);

    // stage tile t into buffer t&1
    auto issue = [&](int t) {
        const float* src0 = mb + t * KS_TILE;
        for (int u = tid; u < C_ * (KS_TILE / 4); u += 192) {   // 1344 16B units
            int c = u >> 6, q = u & 63;
            cp16(&sT[t & 1][c][q * 4], src0 + (size_t)c * HW_ + q * 4);
        }
        CP_COMMIT();
    };

    float acc[4][C_];
    float ss[4];
#pragma unroll
    for (int i = 0; i < 4; i++) {
        ss[i] = 0.f;
#pragma unroll
        for (int c = 0; c < C_; c++) acc[i][c] = 0.f;
    }

    issue(0);
    for (int t = 0; t < KS_NT; t++) {
        if (t + 1 < KS_NT) { issue(t + 1); CP_WAIT1(); } else { CP_WAIT0(); }
        __syncthreads();
        const int buf = t & 1;
#pragma unroll 1
        for (int sub = 0; sub < 4; sub++) {
            const int pr = sub * 32 + lane;       // pixel-pair index in tile
            float2 m2[C_];
#pragma unroll
            for (int c = 0; c < C_; c++)
                m2[c] = reinterpret_cast<const float2*>(sT[buf][c])[pr];
#pragma unroll
            for (int i = 0; i < 4; i++) {
                if (i < nr) {
                    const float2 mr = m2[r0 + i];
                    ss[i] += mr.x + mr.y;
#pragma unroll
                    for (int c = 0; c < C_; c++)
                        acc[i][c] = fmaf(mr.x, m2[c].x, fmaf(mr.y, m2[c].y, acc[i][c]));
                }
            }
        }
        __syncthreads();   // all reads of buf done before it is re-filled
    }

    // reduction: fold 32 -> 8 lanes, stage into sT (reused), final pass
    float* sR = &sT[0][0][0];   // NVAL*9 floats = 16.6 KB, fits
#pragma unroll
    for (int i = 0; i < 4; i++) {
        if (i < nr) {
#pragma unroll
            for (int c = 0; c < C_; c++) {
                float v = acc[i][c];
                v += __shfl_xor_sync(0xffffffffu, v, 16);
                v += __shfl_xor_sync(0xffffffffu, v, 8);
                if (lane < 8) sR[((r0 + i) * C_ + c) * 9 + lane] = v;
            }
            float v = ss[i];
            v += __shfl_xor_sync(0xffffffffu, v, 16);
            v += __shfl_xor_sync(0xffffffffu, v, 8);
            if (lane < 8) sR[(441 + r0 + i) * 9 + lane] = v;
        }
    }
    __syncthreads();

    float* gp = g_Gp + (chunk * B_ + b) * NVAL;
    for (int v = tid; v < NVAL; v += 192) {
        float s = 0.f;
#pragma unroll
        for (int k = 0; k < 8; k++) s += sR[v * 9 + k];
        gp[v] = s;
    }
}

// ---------------- kprep1: W2T[b][c][o] = <conv_w[o,:], feat[b,c,:]> ----------
// grid (8), 256 threads. Weights transposed in smem (padded, conflict-free).
__global__ __launch_bounds__(256) void kprep1(const float* __restrict__ feat,
                                              const float* __restrict__ conv_w) {
    __shared__ float sWT[D_ * 129 + 32];   // [d][o] padded stride 129
    __shared__ float sF[C_ * D_];          // [c][d]
    const int b = blockIdx.x;
    const int tid = threadIdx.x;

    for (int i = tid; i < O_ * D_; i += 256) {
        int o = i >> 6, d = i & 63;
        sWT[d * 129 + o] = conv_w[i];      // coalesced LDG, conflict-free STS
    }
    for (int i = tid; i < C_ * D_; i += 256) sF[i] = feat[b * C_ * D_ + i];
    __syncthreads();

    for (int idx = tid; idx < C_ * O_; idx += 256) {
        int c = idx >> 7, o = idx & 127;
        float s = 0.f;
#pragma unroll
        for (int d = 0; d < D_; d++)
            s = fmaf(sWT[d * 129 + o], sF[c * D_ + d], s);
        g_W2T[b * C_ * O_ + idx] = s;      // coalesced
    }
}

// ---------------- kprep2: reduce partials, analytic BN, fused coeffs ---------
// single block, 256 threads
__global__ __launch_bounds__(256) void kprep2(const float* __restrict__ conv_b,
                                              const float* __restrict__ gamma,
                                              const float* __restrict__ beta) {
    __shared__ float salpha[O_];
    __shared__ float sG[B_ * 441];
    __shared__ float sS[B_ * C_];
    const int tid = threadIdx.x;

    // reduce 32 chunk-partials
    for (int idx = tid; idx < B_ * NVAL; idx += 256) {
        int b = idx / NVAL, v = idx - b * NVAL;
        float s = 0.f;
#pragma unroll
        for (int ch = 0; ch < KS_CHUNKS; ch++) s += g_Gp[(ch * B_ + b) * NVAL + v];
        if (v < 441) sG[b * 441 + v] = s;
        else         sS[b * C_ + (v - 441)] = s;
    }
    __syncthreads();

    if (tid < O_) {
        const int o = tid;
        float sumY = 0.f, sumQ = 0.f;
#pragma unroll 1
        for (int b = 0; b < B_; b++) {
            float w[C_];
#pragma unroll
            for (int c = 0; c < C_; c++) w[c] = g_W2T[(b * C_ + c) * O_ + o];   // coalesced
#pragma unroll
            for (int c = 0; c < C_; c++) sumY = fmaf(w[c], sS[b * C_ + c], sumY);
#pragma unroll
            for (int c = 0; c < C_; c++) {
                float t = 0.f;
#pragma unroll
                for (int c2 = 0; c2 < C_; c2++)
                    t = fmaf(w[c2], sG[b * 441 + c * C_ + c2], t);
                sumQ = fmaf(w[c], t, sumQ);
            }
        }
        const float invN = 1.f / (float)N_TOT;
        const float b0 = conv_b[o];
        const float es = sumY * invN;
        const float mean = b0 + es;
        const float ey2 = sumQ * invN + 2.f * b0 * es + b0 * b0;
        const float var = ey2 - mean * mean;
        const float alpha = gamma[o] * rsqrtf(var + 1e-5f);
        salpha[o] = alpha;
        const float bias2 = beta[o] + alpha * (b0 - mean);
        const uint ub = __float_as_uint(bias2);
        g_bias2[o] = ((ull)ub << 32) | ub;
    }
    __syncthreads();

    for (int idx = tid; idx < B_ * C_ * O_; idx += 256) {
        float v = salpha[idx & 127] * g_W2T[idx];      // coalesced
        uint uv = __float_as_uint(v);
        g_A2[idx] = ((ull)uv << 32) | uv;
    }
}

// ---------------- kmain: persistent fused K=21 GEMM + BN + ReLU --------------
// 296 blocks x 256 threads (2 blocks/SM). Each block owns a contiguous range of
// 128-px subtiles (4096 total), mask double-buffered via cp.async.
// Warp = 16 channels; thread = 1 quad (4 px) x 16 channels.
#define KM_NBLK 296
#define KM_NT   4096        // 8 b * 512 subtiles
#define KM_PX   128

__global__ __launch_bounds__(256, 2) void kmain(const float* __restrict__ mask,
                                                float* __restrict__ out) {
    __shared__ ull sA2[C_ * O_];                       // 21504 B
    __shared__ ull sBias[O_];                          // 1024 B
    __shared__ __align__(16) float sM[2][C_][KM_PX];   // 21504 B

    const int tid = threadIdx.x;
    const int wid = tid >> 5;
    const int lane = tid & 31;
    const int o0 = wid * 16;

    const int bid = blockIdx.x;
    const int t0 = (bid * KM_NT) / KM_NBLK;
    const int t1 = ((bid + 1) * KM_NT) / KM_NBLK;

    if (tid < O_) sBias[tid] = g_bias2[tid];

    auto issue = [&](int s, int buf) {
        const int b = s >> 9;
        const int px = (s & 511) * KM_PX;
        const float* mb = mask + (size_t)b * C_ * HW_ + px;
        for (int u = tid; u < C_ * (KM_PX / 4); u += 256) {   // 672 16B units
            int c = u >> 5, q = u & 31;
            cp16(&sM[buf][c][q * 4], mb + (size_t)c * HW_ + q * 4);
        }
        CP_COMMIT();
    };
    auto stage = [&](int b) {
        for (int i = tid; i < C_ * O_; i += 256) sA2[i] = g_A2[b * C_ * O_ + i];
    };

    int curb = t0 >> 9;
    issue(t0, 0);
    stage(curb);

#pragma unroll 1
    for (int s = t0; s < t1; s++) {
        const int buf = (s - t0) & 1;
        if (s + 1 < t1) { issue(s + 1, buf ^ 1); CP_WAIT1(); } else { CP_WAIT0(); }
        const int b = s >> 9;
        if (b != curb) { __syncthreads(); stage(b); curb = b; }
        __syncthreads();

        ull acc[16][2];
#pragma unroll
        for (int j = 0; j < 16; j++) {
            ull bv = sBias[o0 + j];
            acc[j][0] = bv; acc[j][1] = bv;
        }
#pragma unroll
        for (int c = 0; c < C_; c++) {
            ulonglong2 mq = reinterpret_cast<const ulonglong2*>(sM[buf][c])[lane];
#pragma unroll
            for (int j = 0; j < 16; j++) {
                ull cf = sA2[c * O_ + o0 + j];      // broadcast LDS.64
                asm("fma.rn.f32x2 %0, %1, %2, %0;" : "+l"(acc[j][0]) : "l"(cf), "l"(mq.x));
                asm("fma.rn.f32x2 %0, %1, %2, %0;" : "+l"(acc[j][1]) : "l"(cf), "l"(mq.y));
            }
        }
        __syncthreads();   // release sM[buf] / sA2 before refill

        // epilogue: ReLU + STG.128
        const int px = (s & 511) * KM_PX;
        float* ob = out + (size_t)b * O_ * HW_ + px;
#pragma unroll
        for (int j = 0; j < 16; j++) {
            float2 a0 = *reinterpret_cast<float2*>(&acc[j][0]);
            float2 a1 = *reinterpret_cast<float2*>(&acc[j][1]);
            float4 v = make_float4(fmaxf(a0.x, 0.f), fmaxf(a0.y, 0.f),
                                   fmaxf(a1.x, 0.f), fmaxf(a1.y, 0.f));
            reinterpret_cast<float4*>(ob + (size_t)(o0 + j) * HW_)[lane] = v;
        }
    }
}

// ---------------- launcher ----------------------------------------------------
extern "C" void kernel_launch(void* const* d_in, const int* in_sizes, int n_in,
                              void* d_out, int out_size) {
    const float* feat   = (const float*)d_in[0];
    const float* mask   = (const float*)d_in[1];
    const float* conv_w = (const float*)d_in[2];
    const float* conv_b = (const float*)d_in[3];
    const float* gamma  = (const float*)d_in[4];
    const float* beta   = (const float*)d_in[5];
    float* out = (float*)d_out;

    kstats<<<dim3(KS_CHUNKS, B_), 192>>>(mask);
    kprep1<<<B_, 256>>>(feat, conv_w);
    kprep2<<<1, 256>>>(conv_b, gamma, beta);
    kmain<<<KM_NBLK, 256>>>(mask, out);
}